// round 14
// baseline (speedup 1.0000x reference)
#include <cuda_runtime.h>
#include <cuda_fp16.h>
#include <math.h>

#define NN 50000
#define NE 800000
#define NBLK 196   // ceil(NN/256)
#define POOL_BLOCKS 128

// ---------------- device scratch ----------------
__device__ __align__(16) __half g_h16[2][NN * 64];  // gemm output (UNSCALED), fp16
__device__ __align__(16) float g_a[2][NN * 64];     // agg output, fp32
__device__ int   g_deg[2][NN];
__device__ float g_dinv[2][NN];
__device__ int   g_rowptr[2][NN + 1];
__device__ int   g_rank[2][NE];      // per-edge rank within its dst bucket
__device__ int   g_colidx[2][NE];
__device__ int   g_bsum[2][NBLK];
__device__ float g_cs[2][16];
__device__ float g_evec[2][16];
__device__ int   g_done;

// ---------------- histogram (in-degree) + edge rank capture ----------------
__global__ void hist_kernel(const int* __restrict__ E1, const int* __restrict__ E2) {
    int gi = blockIdx.y;
    const int4* dst = (const int4*)((gi ? E2 : E1) + NE);
    int e4 = blockIdx.x * blockDim.x + threadIdx.x;
    if (e4 < NE / 4) {
        int4 d = dst[e4];
        int4 r;
        r.x = atomicAdd(&g_deg[gi][d.x], 1);
        r.y = atomicAdd(&g_deg[gi][d.y], 1);
        r.z = atomicAdd(&g_deg[gi][d.z], 1);
        r.w = atomicAdd(&g_deg[gi][d.w], 1);
        ((int4*)g_rank[gi])[e4] = r;
    }
}

// ---------------- scan phase A (+ dinv fused; deg NOT zeroed here) ----------------
__global__ void scanA_kernel() {
    int gi = blockIdx.y;
    int bid = blockIdx.x;
    int t = threadIdx.x;
    int idx = bid * 256 + t;
    int v = 0;
    if (idx < NN) {
        v = g_deg[gi][idx];
        g_dinv[gi][idx] = rsqrtf((float)v + 1.0f);
    }
    int lane = t & 31, wid = t >> 5;
    int s = v;
#pragma unroll
    for (int off = 1; off < 32; off <<= 1) {
        int u = __shfl_up_sync(0xffffffffu, s, off);
        if (lane >= off) s += u;
    }
    __shared__ int wsum[8];
    if (lane == 31) wsum[wid] = s;
    __syncthreads();
    if (t < 8) {
        int ws = wsum[t];
#pragma unroll
        for (int off = 1; off < 8; off <<= 1) {
            int u = __shfl_up_sync(0xffu, ws, off);
            if ((t & 7) >= off) ws += u;
        }
        wsum[t] = ws;
    }
    __syncthreads();
    int wpre = wid ? wsum[wid - 1] : 0;
    int excl = wpre + s - v;
    if (idx < NN) g_rowptr[gi][idx] = excl;
    if (t == 255) g_bsum[gi][bid] = wpre + s;
}

__global__ void scanC_kernel() {
    int gi = blockIdx.y;
    int bid = blockIdx.x;
    int t = threadIdx.x;
    __shared__ int sd[256];
    sd[t] = (t < bid) ? g_bsum[gi][t] : 0;
    __syncthreads();
    for (int off = 128; off > 0; off >>= 1) {
        if (t < off) sd[t] += sd[t + off];
        __syncthreads();
    }
    int offset = sd[0];
    int idx = bid * 256 + t;
    if (idx < NN) g_rowptr[gi][idx] += offset;
    if (bid == 0 && t == 0) g_rowptr[gi][NN] = NE;
}

// ---------------- scatter into CSR (atomic-free: rowptr + rank) ----------------
__global__ void scatter_kernel(const int* __restrict__ E1, const int* __restrict__ E2) {
    int gi = blockIdx.y;
    const int* Eg = gi ? E2 : E1;
    const int4* src = (const int4*)Eg;
    const int4* dst = (const int4*)(Eg + NE);
    int e4 = blockIdx.x * blockDim.x + threadIdx.x;
    if (e4 < NE / 4) {
        int4 sv = src[e4];
        int4 dv = dst[e4];
        int4 rv = ((const int4*)g_rank[gi])[e4];
        const int* rp = g_rowptr[gi];
        int* ci = g_colidx[gi];
        ci[rp[dv.x] + rv.x] = sv.x;
        ci[rp[dv.y] + rv.y] = sv.y;
        ci[rp[dv.z] + rv.z] = sv.z;
        ci[rp[dv.w] + rv.w] = sv.w;
    }
}

// ---------------- dense GEMM: g_h16[gi] = fp16(X @ W), unscaled ----------------
// 8 contiguous cols per thread, TR rows per thread, 256 threads.
template <int K, int C, int TR, bool FROMBUF>
__global__ void gemm_kernel(const float* __restrict__ X1, const float* __restrict__ X2,
                            const float* __restrict__ W) {
    constexpr int CT = C / 8;
    constexpr int RT = 256 / CT;
    constexpr int TILE = RT * TR;
    constexpr int KC = 16;
    constexpr int XSTR = TILE + 4;
    __shared__ __align__(16) float Ws[KC][C];
    __shared__ __align__(16) float Xs[KC][XSTR];

    int gi = blockIdx.y;
    const float* X = FROMBUF ? g_a[gi] : (gi ? X2 : X1);
    int row0 = blockIdx.x * TILE;
    int t = threadIdx.x;
    int ct = t % CT, rt = t / CT;

    float acc[TR][8];
#pragma unroll
    for (int i = 0; i < TR; i++)
#pragma unroll
        for (int j = 0; j < 8; j++) acc[i][j] = 0.f;

    for (int k0 = 0; k0 < K; k0 += KC) {
        for (int i = t; i < KC * C; i += 256)
            Ws[i / C][i % C] = W[(k0 + i / C) * C + (i % C)];
        for (int i = t; i < TILE * KC; i += 256) {
            int r = i >> 4, kk = i & 15;
            int gr = row0 + r;
            Xs[kk][r] = (gr < NN) ? X[gr * K + k0 + kk] : 0.f;
        }
        __syncthreads();
#pragma unroll
        for (int kk = 0; kk < KC; kk++) {
            float w[8];
            *(float4*)&w[0] = *(const float4*)&Ws[kk][ct * 8];
            *(float4*)&w[4] = *(const float4*)&Ws[kk][ct * 8 + 4];
            float x[TR];
#pragma unroll
            for (int i = 0; i < TR; i += 4)
                *(float4*)&x[i] = *(const float4*)&Xs[kk][rt * TR + i];
#pragma unroll
            for (int i = 0; i < TR; i++)
#pragma unroll
                for (int j = 0; j < 8; j++)
                    acc[i][j] += x[i] * w[j];
        }
        __syncthreads();
    }
#pragma unroll
    for (int i = 0; i < TR; i++) {
        int gr = row0 + rt * TR + i;
        if (gr < NN) {
            __half2 h2[4];
#pragma unroll
            for (int q = 0; q < 4; q++)
                h2[q] = __floats2half2_rn(acc[i][2 * q], acc[i][2 * q + 1]);
            *(uint4*)&g_h16[gi][gr * C + ct * 8] = *(uint4*)h2;
        }
    }
}

// ---------------- CSR aggregation: a = dinv_d*(sum dinv_c*h_c + dinv_d*h_d) + b ----
// LPN = C/4 threads per node, each handling 4 cols via one uint2 (4 halves).
// dinv table (200KB) is L1-resident; per-edge dinv load is a broadcast hit.
template <int C, bool RELU>
__global__ void agg_kernel(const float* __restrict__ b) {
    constexpr int LPN = C / 4;
    int gi = blockIdx.y;
    int tid = blockIdx.x * blockDim.x + threadIdx.x;
    int node = tid / LPN;
    int chunk = tid - node * LPN;
    if (node >= NN) return;
    int s = g_rowptr[gi][node], e = g_rowptr[gi][node + 1];
    const uint2* h4 = (const uint2*)g_h16[gi];
    const int* ci = g_colidx[gi];
    const float* di = g_dinv[gi];
    float a0[4], a1[4];
#pragma unroll
    for (int j = 0; j < 4; j++) { a0[j] = 0.f; a1[j] = 0.f; }
    int i = s;
    for (; i + 1 < e; i += 2) {
        int c0 = ci[i], c1 = ci[i + 1];
        float v0 = __ldg(&di[c0]);
        float v1 = __ldg(&di[c1]);
        uint2 u0 = h4[c0 * LPN + chunk];
        uint2 u1 = h4[c1 * LPN + chunk];
        float2 f00 = __half22float2(*(const __half2*)&u0.x);
        float2 f01 = __half22float2(*(const __half2*)&u0.y);
        float2 f10 = __half22float2(*(const __half2*)&u1.x);
        float2 f11 = __half22float2(*(const __half2*)&u1.y);
        a0[0] += v0 * f00.x; a0[1] += v0 * f00.y; a0[2] += v0 * f01.x; a0[3] += v0 * f01.y;
        a1[0] += v1 * f10.x; a1[1] += v1 * f10.y; a1[2] += v1 * f11.x; a1[3] += v1 * f11.y;
    }
    if (i < e) {
        int c0 = ci[i];
        float v0 = __ldg(&di[c0]);
        uint2 u0 = h4[c0 * LPN + chunk];
        float2 f00 = __half22float2(*(const __half2*)&u0.x);
        float2 f01 = __half22float2(*(const __half2*)&u0.y);
        a0[0] += v0 * f00.x; a0[1] += v0 * f00.y; a0[2] += v0 * f01.x; a0[3] += v0 * f01.y;
    }
    float dv = di[node];
    // self loop term: + dinv_node * h[node]
    {
        uint2 us = h4[node * LPN + chunk];
        float2 fs0 = __half22float2(*(const __half2*)&us.x);
        float2 fs1 = __half22float2(*(const __half2*)&us.y);
        a0[0] += dv * fs0.x; a0[1] += dv * fs0.y; a0[2] += dv * fs1.x; a0[3] += dv * fs1.y;
    }
    float4 bb = ((const float4*)b)[chunk];
    float4 res;
    res.x = dv * (a0[0] + a1[0]) + bb.x;
    res.y = dv * (a0[1] + a1[1]) + bb.y;
    res.z = dv * (a0[2] + a1[2]) + bb.z;
    res.w = dv * (a0[3] + a1[3]) + bb.w;
    if (RELU) {
        res.x = fmaxf(res.x, 0.f);
        res.y = fmaxf(res.y, 0.f);
        res.z = fmaxf(res.z, 0.f);
        res.w = fmaxf(res.w, 0.f);
    }
    ((float4*)g_a[gi])[node * LPN + chunk] = res;
}

// ---------------- layer-3 aggregation (C=16) + column-sum fusion + deg re-zero ----
__global__ void agg16_kernel(const float* __restrict__ b) {
    int gi = blockIdx.y;
    __shared__ float cssh[16];
    int t = threadIdx.x;
    if (t < 16) cssh[t] = 0.f;
    __syncthreads();
    int tid = blockIdx.x * 256 + t;
    int node = tid >> 2;
    int chunk = tid & 3;
    if (node < NN) {
        int s = g_rowptr[gi][node], e = g_rowptr[gi][node + 1];
        const uint2* h4 = (const uint2*)g_h16[gi];
        const int* ci = g_colidx[gi];
        const float* di = g_dinv[gi];
        float a0[4], a1[4];
#pragma unroll
        for (int j = 0; j < 4; j++) { a0[j] = 0.f; a1[j] = 0.f; }
        int i = s;
        for (; i + 1 < e; i += 2) {
            int c0 = ci[i], c1 = ci[i + 1];
            float v0 = __ldg(&di[c0]);
            float v1 = __ldg(&di[c1]);
            uint2 u0 = h4[c0 * 4 + chunk];
            uint2 u1 = h4[c1 * 4 + chunk];
            float2 f00 = __half22float2(*(const __half2*)&u0.x);
            float2 f01 = __half22float2(*(const __half2*)&u0.y);
            float2 f10 = __half22float2(*(const __half2*)&u1.x);
            float2 f11 = __half22float2(*(const __half2*)&u1.y);
            a0[0] += v0 * f00.x; a0[1] += v0 * f00.y; a0[2] += v0 * f01.x; a0[3] += v0 * f01.y;
            a1[0] += v1 * f10.x; a1[1] += v1 * f10.y; a1[2] += v1 * f11.x; a1[3] += v1 * f11.y;
        }
        if (i < e) {
            int c0 = ci[i];
            float v0 = __ldg(&di[c0]);
            uint2 u0 = h4[c0 * 4 + chunk];
            float2 f00 = __half22float2(*(const __half2*)&u0.x);
            float2 f01 = __half22float2(*(const __half2*)&u0.y);
            a0[0] += v0 * f00.x; a0[1] += v0 * f00.y; a0[2] += v0 * f01.x; a0[3] += v0 * f01.y;
        }
        float dv = di[node];
        {
            uint2 us = h4[node * 4 + chunk];
            float2 fs0 = __half22float2(*(const __half2*)&us.x);
            float2 fs1 = __half22float2(*(const __half2*)&us.y);
            a0[0] += dv * fs0.x; a0[1] += dv * fs0.y; a0[2] += dv * fs1.x; a0[3] += dv * fs1.y;
        }
        float4 bb = ((const float4*)b)[chunk];
        float4 res;
        res.x = dv * (a0[0] + a1[0]) + bb.x;
        res.y = dv * (a0[1] + a1[1]) + bb.y;
        res.z = dv * (a0[2] + a1[2]) + bb.z;
        res.w = dv * (a0[3] + a1[3]) + bb.w;
        ((float4*)g_a[gi])[node * 4 + chunk] = res;
        atomicAdd(&cssh[chunk * 4 + 0], res.x);
        atomicAdd(&cssh[chunk * 4 + 1], res.y);
        atomicAdd(&cssh[chunk * 4 + 2], res.z);
        atomicAdd(&cssh[chunk * 4 + 3], res.w);
        if (chunk == 0) g_deg[gi][node] = 0;   // re-zero deg for next replay
    }
    __syncthreads();
    if (t < 16) atomicAdd(&g_cs[gi][t], cssh[t]);
}

// ---------------- attention pooling (cvec fused) + NTN/MLP tail in last block ----
__global__ void poolfinal_kernel(const float* __restrict__ Wa,
                                 const float* __restrict__ Wt, const float* __restrict__ Wb,
                                 const float* __restrict__ bt, const float* __restrict__ Wfc,
                                 const float* __restrict__ bfc, const float* __restrict__ Wsc,
                                 const float* __restrict__ bsc, float* __restrict__ out) {
    int gi = blockIdx.y;
    __shared__ float csh[16];
    __shared__ float acc[16];
    int t = threadIdx.x;
    if (t < 16) {
        float a = 0.f;
        for (int i = 0; i < 16; i++) a += g_cs[gi][i] * Wa[i * 16 + t];
        csh[t] = tanhf(a * (1.0f / (float)NN));
        acc[t] = 0.f;
    }
    __syncthreads();
    float la[16];
#pragma unroll
    for (int j = 0; j < 16; j++) la[j] = 0.f;
    const float4* base = (const float4*)g_a[gi];
    for (int n = blockIdx.x * blockDim.x + t; n < NN; n += gridDim.x * blockDim.x) {
        const float4* h4 = base + n * 4;
        float hv[16];
#pragma unroll
        for (int j = 0; j < 4; j++) {
            float4 v = h4[j];
            hv[4 * j + 0] = v.x;
            hv[4 * j + 1] = v.y;
            hv[4 * j + 2] = v.z;
            hv[4 * j + 3] = v.w;
        }
        float dot = 0.f;
#pragma unroll
        for (int j = 0; j < 16; j++) dot += hv[j] * csh[j];
        float sg = 1.f / (1.f + __expf(-dot));
#pragma unroll
        for (int j = 0; j < 16; j++) la[j] += sg * hv[j];
    }
#pragma unroll
    for (int j = 0; j < 16; j++) atomicAdd(&acc[j], la[j]);
    __syncthreads();
    if (t < 16) atomicAdd(&g_evec[gi][t], acc[t]);

    // ---- last-block-done: run the NTN + MLP tail ----
    __threadfence();
    __syncthreads();
    __shared__ int is_last;
    if (t == 0) is_last = (atomicAdd(&g_done, 1) == 2 * POOL_BLOCKS - 1) ? 1 : 0;
    __syncthreads();
    if (!is_last) return;

    volatile float* ev0 = g_evec[0];
    volatile float* ev1 = g_evec[1];
    __shared__ float e1s[16], e2s[16], tsh[16], s2[16];
    if (t < 16) {
        e1s[t] = ev0[t];
        e2s[t] = ev1[t];
    }
    __syncthreads();
    if (t < 16) {
        float bil = 0.f;
        for (int i = 0; i < 16; i++) {
            float e1v = e1s[i];
            for (int j = 0; j < 16; j++)
                bil += e1v * Wt[(i * 16 + j) * 16 + t] * e2s[j];
        }
        float blk = 0.f;
        for (int j = 0; j < 16; j++)
            blk += Wb[t * 32 + j] * e1s[j] + Wb[t * 32 + 16 + j] * e2s[j];
        float v = bil + blk + bt[t];
        tsh[t] = v > 0.f ? v : 0.f;
    }
    __syncthreads();
    if (t < 16) {
        float a = bfc[t];
        for (int j = 0; j < 16; j++) a += tsh[j] * Wfc[j * 16 + t];
        s2[t] = tanhf(a);
    }
    __syncthreads();
    if (t == 0) {
        float a = bsc[0];
        for (int j = 0; j < 16; j++) a += s2[j] * Wsc[j];
        out[0] = 1.f / (1.f + expf(-a));
    }
    __syncthreads();
    // re-zero replay state
    if (t < 32) {
        int g = t >> 4, j = t & 15;
        g_cs[g][j] = 0.f;
        g_evec[g][j] = 0.f;
    }
    if (t == 0) g_done = 0;
}

// ---------------- launch ----------------
// side stream: gemm1 at t=0 (no dependencies, unscaled output)
// main stream: hist -> scanA -> scanC -> scatter -> wait(side) -> agg1 ...
extern "C" void kernel_launch(void* const* d_in, const int* in_sizes, int n_in,
                              void* d_out, int out_size) {
    const float* X1  = (const float*)d_in[0];
    const float* X2  = (const float*)d_in[1];
    const int*   E1  = (const int*)d_in[2];
    const int*   E2  = (const int*)d_in[3];
    const float* W1  = (const float*)d_in[4];
    const float* b1  = (const float*)d_in[5];
    const float* W2  = (const float*)d_in[6];
    const float* b2  = (const float*)d_in[7];
    const float* W3  = (const float*)d_in[8];
    const float* b3  = (const float*)d_in[9];
    const float* Wa  = (const float*)d_in[10];
    const float* Wt  = (const float*)d_in[11];
    const float* Wb  = (const float*)d_in[12];
    const float* bt  = (const float*)d_in[13];
    const float* Wfc = (const float*)d_in[14];
    const float* bfc = (const float*)d_in[15];
    const float* Wsc = (const float*)d_in[16];
    const float* bsc = (const float*)d_in[17];
    float* out = (float*)d_out;

    static cudaStream_t s_side = nullptr;
    static cudaEvent_t ev_fork = nullptr, ev_join = nullptr;
    if (s_side == nullptr) {
        cudaStreamCreateWithFlags(&s_side, cudaStreamNonBlocking);
        cudaEventCreateWithFlags(&ev_fork, cudaEventDisableTiming);
        cudaEventCreateWithFlags(&ev_join, cudaEventDisableTiming);
    }

    const int E4B = (NE / 4 + 255) / 256;

    // fork: gemm1 (unscaled) has no dependencies — starts at t=0
    cudaEventRecord(ev_fork, 0);
    cudaStreamWaitEvent(s_side, ev_fork, 0);
    gemm_kernel<96, 64, 8, false><<<dim3((NN + 255) / 256, 2), 256, 0, s_side>>>(X1, X2, W1);
    cudaEventRecord(ev_join, s_side);

    // main stream: full CSR build concurrently
    hist_kernel<<<dim3(E4B, 2), 256>>>(E1, E2);
    scanA_kernel<<<dim3(NBLK, 2), 256>>>();
    scanC_kernel<<<dim3(NBLK, 2), 256>>>();
    scatter_kernel<<<dim3(E4B, 2), 256>>>(E1, E2);

    // join: agg1 needs CSR + dinv (main, ordered) + h (side)
    cudaStreamWaitEvent(0, ev_join, 0);

    agg_kernel<64, true><<<dim3((NN * 16 + 255) / 256, 2), 256>>>(b1);
    // layer 2: 64 -> 32 (relu)
    gemm_kernel<64, 32, 4, true><<<dim3((NN + 255) / 256, 2), 256>>>(nullptr, nullptr, W2);
    agg_kernel<32, true><<<dim3((NN * 8 + 255) / 256, 2), 256>>>(b2);
    // layer 3: 32 -> 16 (no relu), colsum fused, deg re-zeroed
    gemm_kernel<32, 16, 4, true><<<dim3((NN + 511) / 512, 2), 256>>>(nullptr, nullptr, W3);
    agg16_kernel<<<dim3((NN * 4 + 255) / 256, 2), 256>>>(b3);

    poolfinal_kernel<<<dim3(POOL_BLOCKS, 2), 256>>>(Wa, Wt, Wb, bt, Wfc, bfc, Wsc, bsc, out);
}

// round 15
// speedup vs baseline: 1.1623x; 1.1623x over previous
#include <cuda_runtime.h>
#include <cuda_fp16.h>
#include <math.h>

#define NN 50000
#define NE 800000
#define NBLK 196   // ceil(NN/256)
#define POOL_BLOCKS 128

// ---------------- device scratch ----------------
__device__ __align__(16) __half g_h16[2][NN * 64];  // gemm output * dinv, fp16
__device__ __align__(16) float g_a[2][NN * 64];     // agg output, fp32
__device__ int   g_deg[2][NN];
__device__ float g_dinv[2][NN];
__device__ int   g_rowptr[2][NN + 1];
__device__ int   g_rank[2][NE];
__device__ int   g_colidx[2][NE];
__device__ int   g_bsum[2][NBLK];
__device__ float g_cs[2][16];
__device__ float g_evec[2][16];
__device__ int   g_done;

// ---------------- histogram (in-degree) + edge rank capture ----------------
__global__ void hist_kernel(const int* __restrict__ E1, const int* __restrict__ E2) {
    int gi = blockIdx.y;
    const int4* dst = (const int4*)((gi ? E2 : E1) + NE);
    int e4 = blockIdx.x * blockDim.x + threadIdx.x;
    if (e4 < NE / 4) {
        int4 d = dst[e4];
        int4 r;
        r.x = atomicAdd(&g_deg[gi][d.x], 1);
        r.y = atomicAdd(&g_deg[gi][d.y], 1);
        r.z = atomicAdd(&g_deg[gi][d.z], 1);
        r.w = atomicAdd(&g_deg[gi][d.w], 1);
        ((int4*)g_rank[gi])[e4] = r;
    }
}

// ---------------- scan phase A (+ dinv fused; deg NOT zeroed here) ----------------
__global__ void scanA_kernel() {
    int gi = blockIdx.y;
    int bid = blockIdx.x;
    int t = threadIdx.x;
    int idx = bid * 256 + t;
    int v = 0;
    if (idx < NN) {
        v = g_deg[gi][idx];
        g_dinv[gi][idx] = rsqrtf((float)v + 1.0f);
    }
    int lane = t & 31, wid = t >> 5;
    int s = v;
#pragma unroll
    for (int off = 1; off < 32; off <<= 1) {
        int u = __shfl_up_sync(0xffffffffu, s, off);
        if (lane >= off) s += u;
    }
    __shared__ int wsum[8];
    if (lane == 31) wsum[wid] = s;
    __syncthreads();
    if (t < 8) {
        int ws = wsum[t];
#pragma unroll
        for (int off = 1; off < 8; off <<= 1) {
            int u = __shfl_up_sync(0xffu, ws, off);
            if ((t & 7) >= off) ws += u;
        }
        wsum[t] = ws;
    }
    __syncthreads();
    int wpre = wid ? wsum[wid - 1] : 0;
    int excl = wpre + s - v;
    if (idx < NN) g_rowptr[gi][idx] = excl;
    if (t == 255) g_bsum[gi][bid] = wpre + s;
}

__global__ void scanC_kernel() {
    int gi = blockIdx.y;
    int bid = blockIdx.x;
    int t = threadIdx.x;
    __shared__ int sd[256];
    sd[t] = (t < bid) ? g_bsum[gi][t] : 0;
    __syncthreads();
    for (int off = 128; off > 0; off >>= 1) {
        if (t < off) sd[t] += sd[t + off];
        __syncthreads();
    }
    int offset = sd[0];
    int idx = bid * 256 + t;
    if (idx < NN) g_rowptr[gi][idx] += offset;
    if (bid == 0 && t == 0) g_rowptr[gi][NN] = NE;
}

// ---------------- scatter into CSR (atomic-free: rowptr + rank) ----------------
__global__ void scatter_kernel(const int* __restrict__ E1, const int* __restrict__ E2) {
    int gi = blockIdx.y;
    const int* Eg = gi ? E2 : E1;
    const int4* src = (const int4*)Eg;
    const int4* dst = (const int4*)(Eg + NE);
    int e4 = blockIdx.x * blockDim.x + threadIdx.x;
    if (e4 < NE / 4) {
        int4 sv = src[e4];
        int4 dv = dst[e4];
        int4 rv = ((const int4*)g_rank[gi])[e4];
        const int* rp = g_rowptr[gi];
        int* ci = g_colidx[gi];
        ci[rp[dv.x] + rv.x] = sv.x;
        ci[rp[dv.y] + rv.y] = sv.y;
        ci[rp[dv.z] + rv.z] = sv.z;
        ci[rp[dv.w] + rv.w] = sv.w;
    }
}

// ---------------- layer-1 GEMM via tensor cores (mma.sync m16n8k16 fp16) ----------
// g_h16[gi] = fp16((X @ W1) * dinv[row]), dinv computed from deg (SMODE=1 semantics).
// Tile: 128 rows x 64 cols per block, 8 warps (each warp: 16 rows x 64 cols).
#define STRA 104   // 96 + 8 pad (halves) -> conflict-free ldmatrix
#define STRB 72    // 64 + 8 pad

__global__ __launch_bounds__(256) void gemm1_mma_kernel(
    const float* __restrict__ X1, const float* __restrict__ X2,
    const float* __restrict__ W) {
    __shared__ __align__(16) __half As[128 * STRA];
    __shared__ __align__(16) __half Bs[96 * STRB];
    int gi = blockIdx.y;
    const float* X = gi ? X2 : X1;
    int row0 = blockIdx.x * 128;
    int t = threadIdx.x;

    // stage A (128 x 96) fp32 -> fp16 (zero-fill OOB rows)
    for (int i = t; i < 128 * 96; i += 256) {
        int r = i / 96, c = i - r * 96;
        int gr = row0 + r;
        float v = (gr < NN) ? X[gr * 96 + c] : 0.f;
        As[r * STRA + c] = __float2half_rn(v);
    }
    // stage B = W1 (96 x 64) fp32 -> fp16
    for (int i = t; i < 96 * 64; i += 256) {
        int r = i >> 6, c = i & 63;
        Bs[r * STRB + c] = __float2half_rn(W[i]);
    }
    __syncthreads();

    int warp = t >> 5, lane = t & 31;
    int wrow = warp * 16;

    // load all A fragments (6 k-chunks of 16)
    unsigned a[6][4];
#pragma unroll
    for (int kc = 0; kc < 6; kc++) {
        const __half* p = &As[(wrow + (lane & 15)) * STRA + kc * 16 + (lane >> 4) * 8];
        unsigned ad = (unsigned)__cvta_generic_to_shared(p);
        asm volatile("ldmatrix.sync.aligned.m8n8.x4.shared.b16 {%0,%1,%2,%3}, [%4];"
            : "=r"(a[kc][0]), "=r"(a[kc][1]), "=r"(a[kc][2]), "=r"(a[kc][3]) : "r"(ad));
    }

    int r0 = row0 + wrow + (lane >> 2);
    int r1 = r0 + 8;
    float dv0 = (r0 < NN) ? rsqrtf((float)g_deg[gi][r0] + 1.0f) : 0.f;
    float dv1 = (r1 < NN) ? rsqrtf((float)g_deg[gi][r1] + 1.0f) : 0.f;

#pragma unroll
    for (int nt = 0; nt < 8; nt++) {
        float c0 = 0.f, c1 = 0.f, c2 = 0.f, c3 = 0.f;
#pragma unroll
        for (int kc = 0; kc < 6; kc++) {
            int krow = kc * 16 + (lane & 7) + ((lane >> 3) & 1) * 8;
            const __half* pb = &Bs[krow * STRB + nt * 8];
            unsigned bd = (unsigned)__cvta_generic_to_shared(pb);
            unsigned b0, b1;
            asm volatile("ldmatrix.sync.aligned.m8n8.x2.trans.shared.b16 {%0,%1}, [%2];"
                : "=r"(b0), "=r"(b1) : "r"(bd));
            asm volatile("mma.sync.aligned.m16n8k16.row.col.f32.f16.f16.f32 "
                "{%0,%1,%2,%3}, {%4,%5,%6,%7}, {%8,%9}, {%0,%1,%2,%3};"
                : "+f"(c0), "+f"(c1), "+f"(c2), "+f"(c3)
                : "r"(a[kc][0]), "r"(a[kc][1]), "r"(a[kc][2]), "r"(a[kc][3]),
                  "r"(b0), "r"(b1));
        }
        int cc = nt * 8 + (lane & 3) * 2;
        if (r0 < NN)
            *(__half2*)&g_h16[gi][r0 * 64 + cc] = __floats2half2_rn(c0 * dv0, c1 * dv0);
        if (r1 < NN)
            *(__half2*)&g_h16[gi][r1 * 64 + cc] = __floats2half2_rn(c2 * dv1, c3 * dv1);
    }
}

// ---------------- dense scalar GEMM (layers 2,3): g_h16 = fp16((A @ W) * dinv) ----
template <int K, int C, int TR>
__global__ void gemm_kernel(const float* __restrict__ W) {
    constexpr int CT = C / 8;
    constexpr int RT = 256 / CT;
    constexpr int TILE = RT * TR;
    constexpr int KC = 16;
    constexpr int XSTR = TILE + 4;
    __shared__ __align__(16) float Ws[KC][C];
    __shared__ __align__(16) float Xs[KC][XSTR];

    int gi = blockIdx.y;
    const float* X = g_a[gi];
    int row0 = blockIdx.x * TILE;
    int t = threadIdx.x;
    int ct = t % CT, rt = t / CT;

    float acc[TR][8];
#pragma unroll
    for (int i = 0; i < TR; i++)
#pragma unroll
        for (int j = 0; j < 8; j++) acc[i][j] = 0.f;

    for (int k0 = 0; k0 < K; k0 += KC) {
        for (int i = t; i < KC * C; i += 256)
            Ws[i / C][i % C] = W[(k0 + i / C) * C + (i % C)];
        for (int i = t; i < TILE * KC; i += 256) {
            int r = i >> 4, kk = i & 15;
            int gr = row0 + r;
            Xs[kk][r] = (gr < NN) ? X[gr * K + k0 + kk] : 0.f;
        }
        __syncthreads();
#pragma unroll
        for (int kk = 0; kk < KC; kk++) {
            float w[8];
            *(float4*)&w[0] = *(const float4*)&Ws[kk][ct * 8];
            *(float4*)&w[4] = *(const float4*)&Ws[kk][ct * 8 + 4];
            float x[TR];
#pragma unroll
            for (int i = 0; i < TR; i += 4)
                *(float4*)&x[i] = *(const float4*)&Xs[kk][rt * TR + i];
#pragma unroll
            for (int i = 0; i < TR; i++)
#pragma unroll
                for (int j = 0; j < 8; j++)
                    acc[i][j] += x[i] * w[j];
        }
        __syncthreads();
    }
#pragma unroll
    for (int i = 0; i < TR; i++) {
        int gr = row0 + rt * TR + i;
        if (gr < NN) {
            float dv = g_dinv[gi][gr];
            __half2 h2[4];
#pragma unroll
            for (int q = 0; q < 4; q++)
                h2[q] = __floats2half2_rn(acc[i][2 * q] * dv, acc[i][2 * q + 1] * dv);
            *(uint4*)&g_h16[gi][gr * C + ct * 8] = *(uint4*)h2;
        }
    }
}

// ---------------- CSR aggregation: a = dinv_d*(sum h' + h'_d) + b ----------------
template <int C, bool RELU>
__global__ void agg_kernel(const float* __restrict__ b) {
    constexpr int LPN = C / 4;
    int gi = blockIdx.y;
    int tid = blockIdx.x * blockDim.x + threadIdx.x;
    int node = tid / LPN;
    int chunk = tid - node * LPN;
    if (node >= NN) return;
    int s = g_rowptr[gi][node], e = g_rowptr[gi][node + 1];
    const uint2* h4 = (const uint2*)g_h16[gi];
    const int* ci = g_colidx[gi];
    float a0[4], a1[4];
#pragma unroll
    for (int j = 0; j < 4; j++) { a0[j] = 0.f; a1[j] = 0.f; }
    int i = s;
    for (; i + 1 < e; i += 2) {
        int c0 = ci[i], c1 = ci[i + 1];
        uint2 u0 = h4[c0 * LPN + chunk];
        uint2 u1 = h4[c1 * LPN + chunk];
        float2 f00 = __half22float2(*(const __half2*)&u0.x);
        float2 f01 = __half22float2(*(const __half2*)&u0.y);
        float2 f10 = __half22float2(*(const __half2*)&u1.x);
        float2 f11 = __half22float2(*(const __half2*)&u1.y);
        a0[0] += f00.x; a0[1] += f00.y; a0[2] += f01.x; a0[3] += f01.y;
        a1[0] += f10.x; a1[1] += f10.y; a1[2] += f11.x; a1[3] += f11.y;
    }
    if (i < e) {
        int c0 = ci[i];
        uint2 u0 = h4[c0 * LPN + chunk];
        float2 f00 = __half22float2(*(const __half2*)&u0.x);
        float2 f01 = __half22float2(*(const __half2*)&u0.y);
        a0[0] += f00.x; a0[1] += f00.y; a0[2] += f01.x; a0[3] += f01.y;
    }
    {
        uint2 us = h4[node * LPN + chunk];
        float2 fs0 = __half22float2(*(const __half2*)&us.x);
        float2 fs1 = __half22float2(*(const __half2*)&us.y);
        a0[0] += fs0.x; a0[1] += fs0.y; a0[2] += fs1.x; a0[3] += fs1.y;
    }
    float dv = g_dinv[gi][node];
    float4 bb = ((const float4*)b)[chunk];
    float4 res;
    res.x = dv * (a0[0] + a1[0]) + bb.x;
    res.y = dv * (a0[1] + a1[1]) + bb.y;
    res.z = dv * (a0[2] + a1[2]) + bb.z;
    res.w = dv * (a0[3] + a1[3]) + bb.w;
    if (RELU) {
        res.x = fmaxf(res.x, 0.f);
        res.y = fmaxf(res.y, 0.f);
        res.z = fmaxf(res.z, 0.f);
        res.w = fmaxf(res.w, 0.f);
    }
    ((float4*)g_a[gi])[node * LPN + chunk] = res;
}

// ---------------- layer-3 aggregation (C=16) + column-sum fusion + deg re-zero ----
__global__ void agg16_kernel(const float* __restrict__ b) {
    int gi = blockIdx.y;
    __shared__ float cssh[16];
    int t = threadIdx.x;
    if (t < 16) cssh[t] = 0.f;
    __syncthreads();
    int tid = blockIdx.x * 256 + t;
    int node = tid >> 2;
    int chunk = tid & 3;
    if (node < NN) {
        int s = g_rowptr[gi][node], e = g_rowptr[gi][node + 1];
        const uint2* h4 = (const uint2*)g_h16[gi];
        const int* ci = g_colidx[gi];
        float a0[4], a1[4];
#pragma unroll
        for (int j = 0; j < 4; j++) { a0[j] = 0.f; a1[j] = 0.f; }
        int i = s;
        for (; i + 1 < e; i += 2) {
            int c0 = ci[i], c1 = ci[i + 1];
            uint2 u0 = h4[c0 * 4 + chunk];
            uint2 u1 = h4[c1 * 4 + chunk];
            float2 f00 = __half22float2(*(const __half2*)&u0.x);
            float2 f01 = __half22float2(*(const __half2*)&u0.y);
            float2 f10 = __half22float2(*(const __half2*)&u1.x);
            float2 f11 = __half22float2(*(const __half2*)&u1.y);
            a0[0] += f00.x; a0[1] += f00.y; a0[2] += f01.x; a0[3] += f01.y;
            a1[0] += f10.x; a1[1] += f10.y; a1[2] += f11.x; a1[3] += f11.y;
        }
        if (i < e) {
            int c0 = ci[i];
            uint2 u0 = h4[c0 * 4 + chunk];
            float2 f00 = __half22float2(*(const __half2*)&u0.x);
            float2 f01 = __half22float2(*(const __half2*)&u0.y);
            a0[0] += f00.x; a0[1] += f00.y; a0[2] += f01.x; a0[3] += f01.y;
        }
        {
            uint2 us = h4[node * 4 + chunk];
            float2 fs0 = __half22float2(*(const __half2*)&us.x);
            float2 fs1 = __half22float2(*(const __half2*)&us.y);
            a0[0] += fs0.x; a0[1] += fs0.y; a0[2] += fs1.x; a0[3] += fs1.y;
        }
        float dv = g_dinv[gi][node];
        float4 bb = ((const float4*)b)[chunk];
        float4 res;
        res.x = dv * (a0[0] + a1[0]) + bb.x;
        res.y = dv * (a0[1] + a1[1]) + bb.y;
        res.z = dv * (a0[2] + a1[2]) + bb.z;
        res.w = dv * (a0[3] + a1[3]) + bb.w;
        ((float4*)g_a[gi])[node * 4 + chunk] = res;
        atomicAdd(&cssh[chunk * 4 + 0], res.x);
        atomicAdd(&cssh[chunk * 4 + 1], res.y);
        atomicAdd(&cssh[chunk * 4 + 2], res.z);
        atomicAdd(&cssh[chunk * 4 + 3], res.w);
        if (chunk == 0) g_deg[gi][node] = 0;   // re-zero deg for next replay
    }
    __syncthreads();
    if (t < 16) atomicAdd(&g_cs[gi][t], cssh[t]);
}

// ---------------- attention pooling (cvec fused) + NTN/MLP tail in last block ----
__global__ void poolfinal_kernel(const float* __restrict__ Wa,
                                 const float* __restrict__ Wt, const float* __restrict__ Wb,
                                 const float* __restrict__ bt, const float* __restrict__ Wfc,
                                 const float* __restrict__ bfc, const float* __restrict__ Wsc,
                                 const float* __restrict__ bsc, float* __restrict__ out) {
    int gi = blockIdx.y;
    __shared__ float csh[16];
    __shared__ float acc[16];
    int t = threadIdx.x;
    if (t < 16) {
        float a = 0.f;
        for (int i = 0; i < 16; i++) a += g_cs[gi][i] * Wa[i * 16 + t];
        csh[t] = tanhf(a * (1.0f / (float)NN));
        acc[t] = 0.f;
    }
    __syncthreads();
    float la[16];
#pragma unroll
    for (int j = 0; j < 16; j++) la[j] = 0.f;
    const float4* base = (const float4*)g_a[gi];
    for (int n = blockIdx.x * blockDim.x + t; n < NN; n += gridDim.x * blockDim.x) {
        const float4* h4 = base + n * 4;
        float hv[16];
#pragma unroll
        for (int j = 0; j < 4; j++) {
            float4 v = h4[j];
            hv[4 * j + 0] = v.x;
            hv[4 * j + 1] = v.y;
            hv[4 * j + 2] = v.z;
            hv[4 * j + 3] = v.w;
        }
        float dot = 0.f;
#pragma unroll
        for (int j = 0; j < 16; j++) dot += hv[j] * csh[j];
        float sg = 1.f / (1.f + __expf(-dot));
#pragma unroll
        for (int j = 0; j < 16; j++) la[j] += sg * hv[j];
    }
#pragma unroll
    for (int j = 0; j < 16; j++) atomicAdd(&acc[j], la[j]);
    __syncthreads();
    if (t < 16) atomicAdd(&g_evec[gi][t], acc[t]);

    __threadfence();
    __syncthreads();
    __shared__ int is_last;
    if (t == 0) is_last = (atomicAdd(&g_done, 1) == 2 * POOL_BLOCKS - 1) ? 1 : 0;
    __syncthreads();
    if (!is_last) return;

    volatile float* ev0 = g_evec[0];
    volatile float* ev1 = g_evec[1];
    __shared__ float e1s[16], e2s[16], tsh[16], s2[16];
    if (t < 16) {
        e1s[t] = ev0[t];
        e2s[t] = ev1[t];
    }
    __syncthreads();
    if (t < 16) {
        float bil = 0.f;
        for (int i = 0; i < 16; i++) {
            float e1v = e1s[i];
            for (int j = 0; j < 16; j++)
                bil += e1v * Wt[(i * 16 + j) * 16 + t] * e2s[j];
        }
        float blk = 0.f;
        for (int j = 0; j < 16; j++)
            blk += Wb[t * 32 + j] * e1s[j] + Wb[t * 32 + 16 + j] * e2s[j];
        float v = bil + blk + bt[t];
        tsh[t] = v > 0.f ? v : 0.f;
    }
    __syncthreads();
    if (t < 16) {
        float a = bfc[t];
        for (int j = 0; j < 16; j++) a += tsh[j] * Wfc[j * 16 + t];
        s2[t] = tanhf(a);
    }
    __syncthreads();
    if (t == 0) {
        float a = bsc[0];
        for (int j = 0; j < 16; j++) a += s2[j] * Wsc[j];
        out[0] = 1.f / (1.f + expf(-a));
    }
    __syncthreads();
    if (t < 32) {
        int g = t >> 4, j = t & 15;
        g_cs[g][j] = 0.f;
        g_evec[g][j] = 0.f;
    }
    if (t == 0) g_done = 0;
}

// ---------------- launch ----------------
// side stream: [after hist] gemm1_mma (dinv from deg)     (overlaps scanA/scanC/scatter)
// main stream: hist -> scanA -> scanC -> scatter -> wait(side) -> agg1 ...
extern "C" void kernel_launch(void* const* d_in, const int* in_sizes, int n_in,
                              void* d_out, int out_size) {
    const float* X1  = (const float*)d_in[0];
    const float* X2  = (const float*)d_in[1];
    const int*   E1  = (const int*)d_in[2];
    const int*   E2  = (const int*)d_in[3];
    const float* W1  = (const float*)d_in[4];
    const float* b1  = (const float*)d_in[5];
    const float* W2  = (const float*)d_in[6];
    const float* b2  = (const float*)d_in[7];
    const float* W3  = (const float*)d_in[8];
    const float* b3  = (const float*)d_in[9];
    const float* Wa  = (const float*)d_in[10];
    const float* Wt  = (const float*)d_in[11];
    const float* Wb  = (const float*)d_in[12];
    const float* bt  = (const float*)d_in[13];
    const float* Wfc = (const float*)d_in[14];
    const float* bfc = (const float*)d_in[15];
    const float* Wsc = (const float*)d_in[16];
    const float* bsc = (const float*)d_in[17];
    float* out = (float*)d_out;

    static cudaStream_t s_side = nullptr;
    static cudaEvent_t ev_fork = nullptr, ev_join = nullptr;
    if (s_side == nullptr) {
        cudaStreamCreateWithFlags(&s_side, cudaStreamNonBlocking);
        cudaEventCreateWithFlags(&ev_fork, cudaEventDisableTiming);
        cudaEventCreateWithFlags(&ev_join, cudaEventDisableTiming);
    }

    const int E4B = (NE / 4 + 255) / 256;

    // main stream: histogram first (gemm1 needs deg for its dinv epilogue)
    hist_kernel<<<dim3(E4B, 2), 256>>>(E1, E2);

    // fork: tensor-core gemm1 depends only on hist
    cudaEventRecord(ev_fork, 0);
    cudaStreamWaitEvent(s_side, ev_fork, 0);
    gemm1_mma_kernel<<<dim3((NN + 127) / 128, 2), 256, 0, s_side>>>(X1, X2, W1);
    cudaEventRecord(ev_join, s_side);

    // main stream: rest of CSR build concurrently (scatter is atomic-free)
    scanA_kernel<<<dim3(NBLK, 2), 256>>>();
    scanC_kernel<<<dim3(NBLK, 2), 256>>>();
    scatter_kernel<<<dim3(E4B, 2), 256>>>(E1, E2);

    // join: agg1 needs CSR (main, ordered) + h' (side)
    cudaStreamWaitEvent(0, ev_join, 0);

    agg_kernel<64, true><<<dim3((NN * 16 + 255) / 256, 2), 256>>>(b1);
    // layer 2: 64 -> 32 (relu)
    gemm_kernel<64, 32, 4><<<dim3((NN + 255) / 256, 2), 256>>>(W2);
    agg_kernel<32, true><<<dim3((NN * 8 + 255) / 256, 2), 256>>>(b2);
    // layer 3: 32 -> 16 (no relu), colsum fused, deg re-zeroed
    gemm_kernel<32, 16, 4><<<dim3((NN + 511) / 512, 2), 256>>>(W3);
    agg16_kernel<<<dim3((NN * 4 + 255) / 256, 2), 256>>>(b3);

    poolfinal_kernel<<<dim3(POOL_BLOCKS, 2), 256>>>(Wa, Wt, Wb, bt, Wfc, bfc, Wsc, bsc, out);
}

// round 16
// speedup vs baseline: 1.2584x; 1.0827x over previous
#include <cuda_runtime.h>
#include <cuda_fp16.h>
#include <math.h>

#define NN 50000
#define NE 800000
#define NBLK 196   // ceil(NN/256)
#define POOL_BLOCKS 128

// ---------------- device scratch ----------------
__device__ __align__(16) __half g_h16[2][NN * 64];  // gemm output * dinv, fp16
__device__ __align__(16) float g_a[2][NN * 64];     // agg output (fp16 for L1/L2, fp32 for L3)
__device__ int   g_deg[2][NN];
__device__ float g_dinv[2][NN];
__device__ int   g_rowptr[2][NN + 1];
__device__ int   g_rank[2][NE];
__device__ int   g_colidx[2][NE];
__device__ int   g_bsum[2][NBLK];
__device__ float g_cs[2][16];
__device__ float g_evec[2][16];
__device__ int   g_done;

// ---------------- histogram (in-degree) + edge rank capture ----------------
__global__ void hist_kernel(const int* __restrict__ E1, const int* __restrict__ E2) {
    int gi = blockIdx.y;
    const int4* dst = (const int4*)((gi ? E2 : E1) + NE);
    int e4 = blockIdx.x * blockDim.x + threadIdx.x;
    if (e4 < NE / 4) {
        int4 d = dst[e4];
        int4 r;
        r.x = atomicAdd(&g_deg[gi][d.x], 1);
        r.y = atomicAdd(&g_deg[gi][d.y], 1);
        r.z = atomicAdd(&g_deg[gi][d.z], 1);
        r.w = atomicAdd(&g_deg[gi][d.w], 1);
        ((int4*)g_rank[gi])[e4] = r;
    }
}

// ---------------- scan phase A (+ dinv fused; deg NOT zeroed here) ----------------
__global__ void scanA_kernel() {
    int gi = blockIdx.y;
    int bid = blockIdx.x;
    int t = threadIdx.x;
    int idx = bid * 256 + t;
    int v = 0;
    if (idx < NN) {
        v = g_deg[gi][idx];
        g_dinv[gi][idx] = rsqrtf((float)v + 1.0f);
    }
    int lane = t & 31, wid = t >> 5;
    int s = v;
#pragma unroll
    for (int off = 1; off < 32; off <<= 1) {
        int u = __shfl_up_sync(0xffffffffu, s, off);
        if (lane >= off) s += u;
    }
    __shared__ int wsum[8];
    if (lane == 31) wsum[wid] = s;
    __syncthreads();
    if (t < 8) {
        int ws = wsum[t];
#pragma unroll
        for (int off = 1; off < 8; off <<= 1) {
            int u = __shfl_up_sync(0xffu, ws, off);
            if ((t & 7) >= off) ws += u;
        }
        wsum[t] = ws;
    }
    __syncthreads();
    int wpre = wid ? wsum[wid - 1] : 0;
    int excl = wpre + s - v;
    if (idx < NN) g_rowptr[gi][idx] = excl;
    if (t == 255) g_bsum[gi][bid] = wpre + s;
}

__global__ void scanC_kernel() {
    int gi = blockIdx.y;
    int bid = blockIdx.x;
    int t = threadIdx.x;
    __shared__ int sd[256];
    sd[t] = (t < bid) ? g_bsum[gi][t] : 0;
    __syncthreads();
    for (int off = 128; off > 0; off >>= 1) {
        if (t < off) sd[t] += sd[t + off];
        __syncthreads();
    }
    int offset = sd[0];
    int idx = bid * 256 + t;
    if (idx < NN) g_rowptr[gi][idx] += offset;
    if (bid == 0 && t == 0) g_rowptr[gi][NN] = NE;
}

// ---------------- scatter into CSR (atomic-free: rowptr + rank) ----------------
__global__ void scatter_kernel(const int* __restrict__ E1, const int* __restrict__ E2) {
    int gi = blockIdx.y;
    const int* Eg = gi ? E2 : E1;
    const int4* src = (const int4*)Eg;
    const int4* dst = (const int4*)(Eg + NE);
    int e4 = blockIdx.x * blockDim.x + threadIdx.x;
    if (e4 < NE / 4) {
        int4 sv = src[e4];
        int4 dv = dst[e4];
        int4 rv = ((const int4*)g_rank[gi])[e4];
        const int* rp = g_rowptr[gi];
        int* ci = g_colidx[gi];
        ci[rp[dv.x] + rv.x] = sv.x;
        ci[rp[dv.y] + rv.y] = sv.y;
        ci[rp[dv.z] + rv.z] = sv.z;
        ci[rp[dv.w] + rv.w] = sv.w;
    }
}

// ---------------- layer-1 GEMM via tensor cores (mma.sync m16n8k16 fp16) ----------
#define STRA 104   // 96 + 8 pad (halves)
#define STRB 72    // 64 + 8 pad

__global__ __launch_bounds__(256) void gemm1_mma_kernel(
    const float* __restrict__ X1, const float* __restrict__ X2,
    const float* __restrict__ W) {
    __shared__ __align__(16) __half As[128 * STRA];
    __shared__ __align__(16) __half Bs[96 * STRB];
    int gi = blockIdx.y;
    const float* X = gi ? X2 : X1;
    int row0 = blockIdx.x * 128;
    int t = threadIdx.x;

    for (int i = t; i < 128 * 96; i += 256) {
        int r = i / 96, c = i - r * 96;
        int gr = row0 + r;
        float v = (gr < NN) ? X[gr * 96 + c] : 0.f;
        As[r * STRA + c] = __float2half_rn(v);
    }
    for (int i = t; i < 96 * 64; i += 256) {
        int r = i >> 6, c = i & 63;
        Bs[r * STRB + c] = __float2half_rn(W[i]);
    }
    __syncthreads();

    int warp = t >> 5, lane = t & 31;
    int wrow = warp * 16;

    unsigned a[6][4];
#pragma unroll
    for (int kc = 0; kc < 6; kc++) {
        const __half* p = &As[(wrow + (lane & 15)) * STRA + kc * 16 + (lane >> 4) * 8];
        unsigned ad = (unsigned)__cvta_generic_to_shared(p);
        asm volatile("ldmatrix.sync.aligned.m8n8.x4.shared.b16 {%0,%1,%2,%3}, [%4];"
            : "=r"(a[kc][0]), "=r"(a[kc][1]), "=r"(a[kc][2]), "=r"(a[kc][3]) : "r"(ad));
    }

    int r0 = row0 + wrow + (lane >> 2);
    int r1 = r0 + 8;
    float dv0 = (r0 < NN) ? rsqrtf((float)g_deg[gi][r0] + 1.0f) : 0.f;
    float dv1 = (r1 < NN) ? rsqrtf((float)g_deg[gi][r1] + 1.0f) : 0.f;

#pragma unroll
    for (int nt = 0; nt < 8; nt++) {
        float c0 = 0.f, c1 = 0.f, c2 = 0.f, c3 = 0.f;
#pragma unroll
        for (int kc = 0; kc < 6; kc++) {
            int krow = kc * 16 + (lane & 7) + ((lane >> 3) & 1) * 8;
            const __half* pb = &Bs[krow * STRB + nt * 8];
            unsigned bd = (unsigned)__cvta_generic_to_shared(pb);
            unsigned b0, b1;
            asm volatile("ldmatrix.sync.aligned.m8n8.x2.trans.shared.b16 {%0,%1}, [%2];"
                : "=r"(b0), "=r"(b1) : "r"(bd));
            asm volatile("mma.sync.aligned.m16n8k16.row.col.f32.f16.f16.f32 "
                "{%0,%1,%2,%3}, {%4,%5,%6,%7}, {%8,%9}, {%0,%1,%2,%3};"
                : "+f"(c0), "+f"(c1), "+f"(c2), "+f"(c3)
                : "r"(a[kc][0]), "r"(a[kc][1]), "r"(a[kc][2]), "r"(a[kc][3]),
                  "r"(b0), "r"(b1));
        }
        int cc = nt * 8 + (lane & 3) * 2;
        if (r0 < NN)
            *(__half2*)&g_h16[gi][r0 * 64 + cc] = __floats2half2_rn(c0 * dv0, c1 * dv0);
        if (r1 < NN)
            *(__half2*)&g_h16[gi][r1 * 64 + cc] = __floats2half2_rn(c2 * dv1, c3 * dv1);
    }
}

// ---------------- layer-2/3 GEMM via tensor cores (fp16 input from g_a) ----------
// g_h16[gi] = fp16((A16 @ W) * dinv[row]);  A16 = fp16 activations in g_a.
template <int K, int C>
__global__ __launch_bounds__(256) void gemm_mma_kernel(const float* __restrict__ W) {
    constexpr int KCH = K / 16;
    constexpr int NT = C / 8;
    constexpr int SA = K + 8;
    constexpr int SB = C + 8;
    __shared__ __align__(16) __half As[128 * SA];
    __shared__ __align__(16) __half Bs[K * SB];
    int gi = blockIdx.y;
    const __half* Xh = (const __half*)g_a[gi];
    int row0 = blockIdx.x * 128;
    int t = threadIdx.x;

    // stage A: direct fp16 copy, 8 halves per uint4
    for (int i = t; i < 128 * (K / 8); i += 256) {
        int r = i / (K / 8), c8 = i - r * (K / 8);
        int gr = row0 + r;
        uint4 v = make_uint4(0u, 0u, 0u, 0u);
        if (gr < NN) v = *(const uint4*)&Xh[gr * K + c8 * 8];
        *(uint4*)&As[r * SA + c8 * 8] = v;
    }
    // stage B: W (K x C) fp32 -> fp16
    for (int i = t; i < K * C; i += 256) {
        int r = i / C, c = i - r * C;
        Bs[r * SB + c] = __float2half_rn(W[i]);
    }
    __syncthreads();

    int warp = t >> 5, lane = t & 31;
    int wrow = warp * 16;

    unsigned a[KCH][4];
#pragma unroll
    for (int kc = 0; kc < KCH; kc++) {
        const __half* p = &As[(wrow + (lane & 15)) * SA + kc * 16 + (lane >> 4) * 8];
        unsigned ad = (unsigned)__cvta_generic_to_shared(p);
        asm volatile("ldmatrix.sync.aligned.m8n8.x4.shared.b16 {%0,%1,%2,%3}, [%4];"
            : "=r"(a[kc][0]), "=r"(a[kc][1]), "=r"(a[kc][2]), "=r"(a[kc][3]) : "r"(ad));
    }

    int r0 = row0 + wrow + (lane >> 2);
    int r1 = r0 + 8;
    float dv0 = (r0 < NN) ? g_dinv[gi][r0] : 0.f;
    float dv1 = (r1 < NN) ? g_dinv[gi][r1] : 0.f;

#pragma unroll
    for (int nt = 0; nt < NT; nt++) {
        float c0 = 0.f, c1 = 0.f, c2 = 0.f, c3 = 0.f;
#pragma unroll
        for (int kc = 0; kc < KCH; kc++) {
            int krow = kc * 16 + (lane & 7) + ((lane >> 3) & 1) * 8;
            const __half* pb = &Bs[krow * SB + nt * 8];
            unsigned bd = (unsigned)__cvta_generic_to_shared(pb);
            unsigned b0, b1;
            asm volatile("ldmatrix.sync.aligned.m8n8.x2.trans.shared.b16 {%0,%1}, [%2];"
                : "=r"(b0), "=r"(b1) : "r"(bd));
            asm volatile("mma.sync.aligned.m16n8k16.row.col.f32.f16.f16.f32 "
                "{%0,%1,%2,%3}, {%4,%5,%6,%7}, {%8,%9}, {%0,%1,%2,%3};"
                : "+f"(c0), "+f"(c1), "+f"(c2), "+f"(c3)
                : "r"(a[kc][0]), "r"(a[kc][1]), "r"(a[kc][2]), "r"(a[kc][3]),
                  "r"(b0), "r"(b1));
        }
        int cc = nt * 8 + (lane & 3) * 2;
        if (r0 < NN)
            *(__half2*)&g_h16[gi][r0 * C + cc] = __floats2half2_rn(c0 * dv0, c1 * dv0);
        if (r1 < NN)
            *(__half2*)&g_h16[gi][r1 * C + cc] = __floats2half2_rn(c2 * dv1, c3 * dv1);
    }
}

// ---------------- CSR aggregation: a16 = relu(dinv_d*(sum h' + h'_d) + b) ----------
// Writes fp16 activations (consumed by mma gemm).
template <int C, bool RELU>
__global__ void agg_kernel(const float* __restrict__ b) {
    constexpr int LPN = C / 4;
    int gi = blockIdx.y;
    int tid = blockIdx.x * blockDim.x + threadIdx.x;
    int node = tid / LPN;
    int chunk = tid - node * LPN;
    if (node >= NN) return;
    int s = g_rowptr[gi][node], e = g_rowptr[gi][node + 1];
    const uint2* h4 = (const uint2*)g_h16[gi];
    const int* ci = g_colidx[gi];
    float a0[4], a1[4];
#pragma unroll
    for (int j = 0; j < 4; j++) { a0[j] = 0.f; a1[j] = 0.f; }
    int i = s;
    for (; i + 1 < e; i += 2) {
        int c0 = ci[i], c1 = ci[i + 1];
        uint2 u0 = h4[c0 * LPN + chunk];
        uint2 u1 = h4[c1 * LPN + chunk];
        float2 f00 = __half22float2(*(const __half2*)&u0.x);
        float2 f01 = __half22float2(*(const __half2*)&u0.y);
        float2 f10 = __half22float2(*(const __half2*)&u1.x);
        float2 f11 = __half22float2(*(const __half2*)&u1.y);
        a0[0] += f00.x; a0[1] += f00.y; a0[2] += f01.x; a0[3] += f01.y;
        a1[0] += f10.x; a1[1] += f10.y; a1[2] += f11.x; a1[3] += f11.y;
    }
    if (i < e) {
        int c0 = ci[i];
        uint2 u0 = h4[c0 * LPN + chunk];
        float2 f00 = __half22float2(*(const __half2*)&u0.x);
        float2 f01 = __half22float2(*(const __half2*)&u0.y);
        a0[0] += f00.x; a0[1] += f00.y; a0[2] += f01.x; a0[3] += f01.y;
    }
    {
        uint2 us = h4[node * LPN + chunk];
        float2 fs0 = __half22float2(*(const __half2*)&us.x);
        float2 fs1 = __half22float2(*(const __half2*)&us.y);
        a0[0] += fs0.x; a0[1] += fs0.y; a0[2] += fs1.x; a0[3] += fs1.y;
    }
    float dv = g_dinv[gi][node];
    float4 bb = ((const float4*)b)[chunk];
    float4 res;
    res.x = dv * (a0[0] + a1[0]) + bb.x;
    res.y = dv * (a0[1] + a1[1]) + bb.y;
    res.z = dv * (a0[2] + a1[2]) + bb.z;
    res.w = dv * (a0[3] + a1[3]) + bb.w;
    if (RELU) {
        res.x = fmaxf(res.x, 0.f);
        res.y = fmaxf(res.y, 0.f);
        res.z = fmaxf(res.z, 0.f);
        res.w = fmaxf(res.w, 0.f);
    }
    __half2 o0 = __floats2half2_rn(res.x, res.y);
    __half2 o1 = __floats2half2_rn(res.z, res.w);
    uint2 ov;
    ov.x = *(unsigned*)&o0;
    ov.y = *(unsigned*)&o1;
    ((uint2*)g_a[gi])[node * LPN + chunk] = ov;
}

// ---------------- layer-3 aggregation (C=16) + column-sum fusion + deg re-zero ----
// Writes fp32 (consumed by poolfinal).
__global__ void agg16_kernel(const float* __restrict__ b) {
    int gi = blockIdx.y;
    __shared__ float cssh[16];
    int t = threadIdx.x;
    if (t < 16) cssh[t] = 0.f;
    __syncthreads();
    int tid = blockIdx.x * 256 + t;
    int node = tid >> 2;
    int chunk = tid & 3;
    if (node < NN) {
        int s = g_rowptr[gi][node], e = g_rowptr[gi][node + 1];
        const uint2* h4 = (const uint2*)g_h16[gi];
        const int* ci = g_colidx[gi];
        float a0[4], a1[4];
#pragma unroll
        for (int j = 0; j < 4; j++) { a0[j] = 0.f; a1[j] = 0.f; }
        int i = s;
        for (; i + 1 < e; i += 2) {
            int c0 = ci[i], c1 = ci[i + 1];
            uint2 u0 = h4[c0 * 4 + chunk];
            uint2 u1 = h4[c1 * 4 + chunk];
            float2 f00 = __half22float2(*(const __half2*)&u0.x);
            float2 f01 = __half22float2(*(const __half2*)&u0.y);
            float2 f10 = __half22float2(*(const __half2*)&u1.x);
            float2 f11 = __half22float2(*(const __half2*)&u1.y);
            a0[0] += f00.x; a0[1] += f00.y; a0[2] += f01.x; a0[3] += f01.y;
            a1[0] += f10.x; a1[1] += f10.y; a1[2] += f11.x; a1[3] += f11.y;
        }
        if (i < e) {
            int c0 = ci[i];
            uint2 u0 = h4[c0 * 4 + chunk];
            float2 f00 = __half22float2(*(const __half2*)&u0.x);
            float2 f01 = __half22float2(*(const __half2*)&u0.y);
            a0[0] += f00.x; a0[1] += f00.y; a0[2] += f01.x; a0[3] += f01.y;
        }
        {
            uint2 us = h4[node * 4 + chunk];
            float2 fs0 = __half22float2(*(const __half2*)&us.x);
            float2 fs1 = __half22float2(*(const __half2*)&us.y);
            a0[0] += fs0.x; a0[1] += fs0.y; a0[2] += fs1.x; a0[3] += fs1.y;
        }
        float dv = g_dinv[gi][node];
        float4 bb = ((const float4*)b)[chunk];
        float4 res;
        res.x = dv * (a0[0] + a1[0]) + bb.x;
        res.y = dv * (a0[1] + a1[1]) + bb.y;
        res.z = dv * (a0[2] + a1[2]) + bb.z;
        res.w = dv * (a0[3] + a1[3]) + bb.w;
        ((float4*)g_a[gi])[node * 4 + chunk] = res;
        atomicAdd(&cssh[chunk * 4 + 0], res.x);
        atomicAdd(&cssh[chunk * 4 + 1], res.y);
        atomicAdd(&cssh[chunk * 4 + 2], res.z);
        atomicAdd(&cssh[chunk * 4 + 3], res.w);
        if (chunk == 0) g_deg[gi][node] = 0;   // re-zero deg for next replay
    }
    __syncthreads();
    if (t < 16) atomicAdd(&g_cs[gi][t], cssh[t]);
}

// ---------------- attention pooling (cvec fused) + NTN/MLP tail in last block ----
__global__ void poolfinal_kernel(const float* __restrict__ Wa,
                                 const float* __restrict__ Wt, const float* __restrict__ Wb,
                                 const float* __restrict__ bt, const float* __restrict__ Wfc,
                                 const float* __restrict__ bfc, const float* __restrict__ Wsc,
                                 const float* __restrict__ bsc, float* __restrict__ out) {
    int gi = blockIdx.y;
    __shared__ float csh[16];
    __shared__ float acc[16];
    int t = threadIdx.x;
    if (t < 16) {
        float a = 0.f;
        for (int i = 0; i < 16; i++) a += g_cs[gi][i] * Wa[i * 16 + t];
        csh[t] = tanhf(a * (1.0f / (float)NN));
        acc[t] = 0.f;
    }
    __syncthreads();
    float la[16];
#pragma unroll
    for (int j = 0; j < 16; j++) la[j] = 0.f;
    const float4* base = (const float4*)g_a[gi];
    for (int n = blockIdx.x * blockDim.x + t; n < NN; n += gridDim.x * blockDim.x) {
        const float4* h4 = base + n * 4;
        float hv[16];
#pragma unroll
        for (int j = 0; j < 4; j++) {
            float4 v = h4[j];
            hv[4 * j + 0] = v.x;
            hv[4 * j + 1] = v.y;
            hv[4 * j + 2] = v.z;
            hv[4 * j + 3] = v.w;
        }
        float dot = 0.f;
#pragma unroll
        for (int j = 0; j < 16; j++) dot += hv[j] * csh[j];
        float sg = 1.f / (1.f + __expf(-dot));
#pragma unroll
        for (int j = 0; j < 16; j++) la[j] += sg * hv[j];
    }
#pragma unroll
    for (int j = 0; j < 16; j++) atomicAdd(&acc[j], la[j]);
    __syncthreads();
    if (t < 16) atomicAdd(&g_evec[gi][t], acc[t]);

    __threadfence();
    __syncthreads();
    __shared__ int is_last;
    if (t == 0) is_last = (atomicAdd(&g_done, 1) == 2 * POOL_BLOCKS - 1) ? 1 : 0;
    __syncthreads();
    if (!is_last) return;

    volatile float* ev0 = g_evec[0];
    volatile float* ev1 = g_evec[1];
    __shared__ float e1s[16], e2s[16], tsh[16], s2[16];
    if (t < 16) {
        e1s[t] = ev0[t];
        e2s[t] = ev1[t];
    }
    __syncthreads();
    if (t < 16) {
        float bil = 0.f;
        for (int i = 0; i < 16; i++) {
            float e1v = e1s[i];
            for (int j = 0; j < 16; j++)
                bil += e1v * Wt[(i * 16 + j) * 16 + t] * e2s[j];
        }
        float blk = 0.f;
        for (int j = 0; j < 16; j++)
            blk += Wb[t * 32 + j] * e1s[j] + Wb[t * 32 + 16 + j] * e2s[j];
        float v = bil + blk + bt[t];
        tsh[t] = v > 0.f ? v : 0.f;
    }
    __syncthreads();
    if (t < 16) {
        float a = bfc[t];
        for (int j = 0; j < 16; j++) a += tsh[j] * Wfc[j * 16 + t];
        s2[t] = tanhf(a);
    }
    __syncthreads();
    if (t == 0) {
        float a = bsc[0];
        for (int j = 0; j < 16; j++) a += s2[j] * Wsc[j];
        out[0] = 1.f / (1.f + expf(-a));
    }
    __syncthreads();
    if (t < 32) {
        int g = t >> 4, j = t & 15;
        g_cs[g][j] = 0.f;
        g_evec[g][j] = 0.f;
    }
    if (t == 0) g_done = 0;
}

// ---------------- launch ----------------
extern "C" void kernel_launch(void* const* d_in, const int* in_sizes, int n_in,
                              void* d_out, int out_size) {
    const float* X1  = (const float*)d_in[0];
    const float* X2  = (const float*)d_in[1];
    const int*   E1  = (const int*)d_in[2];
    const int*   E2  = (const int*)d_in[3];
    const float* W1  = (const float*)d_in[4];
    const float* b1  = (const float*)d_in[5];
    const float* W2  = (const float*)d_in[6];
    const float* b2  = (const float*)d_in[7];
    const float* W3  = (const float*)d_in[8];
    const float* b3  = (const float*)d_in[9];
    const float* Wa  = (const float*)d_in[10];
    const float* Wt  = (const float*)d_in[11];
    const float* Wb  = (const float*)d_in[12];
    const float* bt  = (const float*)d_in[13];
    const float* Wfc = (const float*)d_in[14];
    const float* bfc = (const float*)d_in[15];
    const float* Wsc = (const float*)d_in[16];
    const float* bsc = (const float*)d_in[17];
    float* out = (float*)d_out;

    static cudaStream_t s_side = nullptr;
    static cudaEvent_t ev_fork = nullptr, ev_join = nullptr;
    if (s_side == nullptr) {
        cudaStreamCreateWithFlags(&s_side, cudaStreamNonBlocking);
        cudaEventCreateWithFlags(&ev_fork, cudaEventDisableTiming);
        cudaEventCreateWithFlags(&ev_join, cudaEventDisableTiming);
    }

    const int E4B = (NE / 4 + 255) / 256;

    // main stream: histogram first (gemm1 needs deg for its dinv epilogue)
    hist_kernel<<<dim3(E4B, 2), 256>>>(E1, E2);

    // fork: tensor-core gemm1 depends only on hist
    cudaEventRecord(ev_fork, 0);
    cudaStreamWaitEvent(s_side, ev_fork, 0);
    gemm1_mma_kernel<<<dim3((NN + 127) / 128, 2), 256, 0, s_side>>>(X1, X2, W1);
    cudaEventRecord(ev_join, s_side);

    // main stream: rest of CSR build concurrently (scatter is atomic-free)
    scanA_kernel<<<dim3(NBLK, 2), 256>>>();
    scanC_kernel<<<dim3(NBLK, 2), 256>>>();
    scatter_kernel<<<dim3(E4B, 2), 256>>>(E1, E2);

    // join: agg1 needs CSR (main, ordered) + h' (side)
    cudaStreamWaitEvent(0, ev_join, 0);

    agg_kernel<64, true><<<dim3((NN * 16 + 255) / 256, 2), 256>>>(b1);
    // layer 2: 64 -> 32 (relu), tensor-core
    gemm_mma_kernel<64, 32><<<dim3((NN + 127) / 128, 2), 256>>>(W2);
    agg_kernel<32, true><<<dim3((NN * 8 + 255) / 256, 2), 256>>>(b2);
    // layer 3: 32 -> 16 (no relu), tensor-core; colsum fused in agg16
    gemm_mma_kernel<32, 16><<<dim3((NN + 127) / 128, 2), 256>>>(W3);
    agg16_kernel<<<dim3((NN * 4 + 255) / 256, 2), 256>>>(b3);

    poolfinal_kernel<<<dim3(POOL_BLOCKS, 2), 256>>>(Wa, Wt, Wb, bt, Wfc, bfc, Wsc, bsc, out);
}

// round 17
// speedup vs baseline: 1.2704x; 1.0095x over previous
#include <cuda_runtime.h>
#include <cuda_fp16.h>
#include <math.h>

#define NN 50000
#define NE 800000
#define NBLK 196   // ceil(NN/256)
#define POOL_BLOCKS 128

// ---------------- device scratch ----------------
__device__ __align__(16) __half g_h16[2][NN * 64];  // gemm output * dinv, fp16
__device__ __align__(16) float g_a[2][NN * 64];     // activations (fp16 everywhere now)
__device__ int   g_deg[2][NN];
__device__ float g_dinv[2][NN];
__device__ int   g_rowptr[2][NN + 1];
__device__ int   g_rank[2][NE];
__device__ int   g_colidx[2][NE];
__device__ int   g_bsum[2][NBLK];
__device__ float g_cs[2][16];
__device__ float g_evec[2][16];
__device__ int   g_done;

// ---------------- histogram (in-degree) + edge rank capture ----------------
__global__ void hist_kernel(const int* __restrict__ E1, const int* __restrict__ E2) {
    int gi = blockIdx.y;
    const int4* dst = (const int4*)((gi ? E2 : E1) + NE);
    int e4 = blockIdx.x * blockDim.x + threadIdx.x;
    if (e4 < NE / 4) {
        int4 d = dst[e4];
        int4 r;
        r.x = atomicAdd(&g_deg[gi][d.x], 1);
        r.y = atomicAdd(&g_deg[gi][d.y], 1);
        r.z = atomicAdd(&g_deg[gi][d.z], 1);
        r.w = atomicAdd(&g_deg[gi][d.w], 1);
        ((int4*)g_rank[gi])[e4] = r;
    }
}

// ---------------- scan phase A (+ dinv fused; deg NOT zeroed here) ----------------
__global__ void scanA_kernel() {
    int gi = blockIdx.y;
    int bid = blockIdx.x;
    int t = threadIdx.x;
    int idx = bid * 256 + t;
    int v = 0;
    if (idx < NN) {
        v = g_deg[gi][idx];
        g_dinv[gi][idx] = rsqrtf((float)v + 1.0f);
    }
    int lane = t & 31, wid = t >> 5;
    int s = v;
#pragma unroll
    for (int off = 1; off < 32; off <<= 1) {
        int u = __shfl_up_sync(0xffffffffu, s, off);
        if (lane >= off) s += u;
    }
    __shared__ int wsum[8];
    if (lane == 31) wsum[wid] = s;
    __syncthreads();
    if (t < 8) {
        int ws = wsum[t];
#pragma unroll
        for (int off = 1; off < 8; off <<= 1) {
            int u = __shfl_up_sync(0xffu, ws, off);
            if ((t & 7) >= off) ws += u;
        }
        wsum[t] = ws;
    }
    __syncthreads();
    int wpre = wid ? wsum[wid - 1] : 0;
    int excl = wpre + s - v;
    if (idx < NN) g_rowptr[gi][idx] = excl;
    if (t == 255) g_bsum[gi][bid] = wpre + s;
}

__global__ void scanC_kernel() {
    int gi = blockIdx.y;
    int bid = blockIdx.x;
    int t = threadIdx.x;
    __shared__ int sd[256];
    sd[t] = (t < bid) ? g_bsum[gi][t] : 0;
    __syncthreads();
    for (int off = 128; off > 0; off >>= 1) {
        if (t < off) sd[t] += sd[t + off];
        __syncthreads();
    }
    int offset = sd[0];
    int idx = bid * 256 + t;
    if (idx < NN) g_rowptr[gi][idx] += offset;
    if (bid == 0 && t == 0) g_rowptr[gi][NN] = NE;
}

// ---------------- scatter into CSR (atomic-free: rowptr + rank) ----------------
__global__ void scatter_kernel(const int* __restrict__ E1, const int* __restrict__ E2) {
    int gi = blockIdx.y;
    const int* Eg = gi ? E2 : E1;
    const int4* src = (const int4*)Eg;
    const int4* dst = (const int4*)(Eg + NE);
    int e4 = blockIdx.x * blockDim.x + threadIdx.x;
    if (e4 < NE / 4) {
        int4 sv = src[e4];
        int4 dv = dst[e4];
        int4 rv = ((const int4*)g_rank[gi])[e4];
        const int* rp = g_rowptr[gi];
        int* ci = g_colidx[gi];
        ci[rp[dv.x] + rv.x] = sv.x;
        ci[rp[dv.y] + rv.y] = sv.y;
        ci[rp[dv.z] + rv.z] = sv.z;
        ci[rp[dv.w] + rv.w] = sv.w;
    }
}

// ---------------- layer-1 GEMM via tensor cores (mma.sync m16n8k16 fp16) ----------
#define STRA 104
#define STRB 72

__global__ __launch_bounds__(256) void gemm1_mma_kernel(
    const float* __restrict__ X1, const float* __restrict__ X2,
    const float* __restrict__ W) {
    __shared__ __align__(16) __half As[128 * STRA];
    __shared__ __align__(16) __half Bs[96 * STRB];
    int gi = blockIdx.y;
    const float* X = gi ? X2 : X1;
    int row0 = blockIdx.x * 128;
    int t = threadIdx.x;

    for (int i = t; i < 128 * 96; i += 256) {
        int r = i / 96, c = i - r * 96;
        int gr = row0 + r;
        float v = (gr < NN) ? X[gr * 96 + c] : 0.f;
        As[r * STRA + c] = __float2half_rn(v);
    }
    for (int i = t; i < 96 * 64; i += 256) {
        int r = i >> 6, c = i & 63;
        Bs[r * STRB + c] = __float2half_rn(W[i]);
    }
    __syncthreads();

    int warp = t >> 5, lane = t & 31;
    int wrow = warp * 16;

    unsigned a[6][4];
#pragma unroll
    for (int kc = 0; kc < 6; kc++) {
        const __half* p = &As[(wrow + (lane & 15)) * STRA + kc * 16 + (lane >> 4) * 8];
        unsigned ad = (unsigned)__cvta_generic_to_shared(p);
        asm volatile("ldmatrix.sync.aligned.m8n8.x4.shared.b16 {%0,%1,%2,%3}, [%4];"
            : "=r"(a[kc][0]), "=r"(a[kc][1]), "=r"(a[kc][2]), "=r"(a[kc][3]) : "r"(ad));
    }

    int r0 = row0 + wrow + (lane >> 2);
    int r1 = r0 + 8;
    float dv0 = (r0 < NN) ? rsqrtf((float)g_deg[gi][r0] + 1.0f) : 0.f;
    float dv1 = (r1 < NN) ? rsqrtf((float)g_deg[gi][r1] + 1.0f) : 0.f;

#pragma unroll
    for (int nt = 0; nt < 8; nt++) {
        float c0 = 0.f, c1 = 0.f, c2 = 0.f, c3 = 0.f;
#pragma unroll
        for (int kc = 0; kc < 6; kc++) {
            int krow = kc * 16 + (lane & 7) + ((lane >> 3) & 1) * 8;
            const __half* pb = &Bs[krow * STRB + nt * 8];
            unsigned bd = (unsigned)__cvta_generic_to_shared(pb);
            unsigned b0, b1;
            asm volatile("ldmatrix.sync.aligned.m8n8.x2.trans.shared.b16 {%0,%1}, [%2];"
                : "=r"(b0), "=r"(b1) : "r"(bd));
            asm volatile("mma.sync.aligned.m16n8k16.row.col.f32.f16.f16.f32 "
                "{%0,%1,%2,%3}, {%4,%5,%6,%7}, {%8,%9}, {%0,%1,%2,%3};"
                : "+f"(c0), "+f"(c1), "+f"(c2), "+f"(c3)
                : "r"(a[kc][0]), "r"(a[kc][1]), "r"(a[kc][2]), "r"(a[kc][3]),
                  "r"(b0), "r"(b1));
        }
        int cc = nt * 8 + (lane & 3) * 2;
        if (r0 < NN)
            *(__half2*)&g_h16[gi][r0 * 64 + cc] = __floats2half2_rn(c0 * dv0, c1 * dv0);
        if (r1 < NN)
            *(__half2*)&g_h16[gi][r1 * 64 + cc] = __floats2half2_rn(c2 * dv1, c3 * dv1);
    }
}

// ---------------- layer-2/3 GEMM via tensor cores (fp16 input from g_a) ----------
template <int K, int C>
__global__ __launch_bounds__(256) void gemm_mma_kernel(const float* __restrict__ W) {
    constexpr int KCH = K / 16;
    constexpr int NT = C / 8;
    constexpr int SA = K + 8;
    constexpr int SB = C + 8;
    __shared__ __align__(16) __half As[128 * SA];
    __shared__ __align__(16) __half Bs[K * SB];
    int gi = blockIdx.y;
    const __half* Xh = (const __half*)g_a[gi];
    int row0 = blockIdx.x * 128;
    int t = threadIdx.x;

    for (int i = t; i < 128 * (K / 8); i += 256) {
        int r = i / (K / 8), c8 = i - r * (K / 8);
        int gr = row0 + r;
        uint4 v = make_uint4(0u, 0u, 0u, 0u);
        if (gr < NN) v = *(const uint4*)&Xh[gr * K + c8 * 8];
        *(uint4*)&As[r * SA + c8 * 8] = v;
    }
    for (int i = t; i < K * C; i += 256) {
        int r = i / C, c = i - r * C;
        Bs[r * SB + c] = __float2half_rn(W[i]);
    }
    __syncthreads();

    int warp = t >> 5, lane = t & 31;
    int wrow = warp * 16;

    unsigned a[KCH][4];
#pragma unroll
    for (int kc = 0; kc < KCH; kc++) {
        const __half* p = &As[(wrow + (lane & 15)) * SA + kc * 16 + (lane >> 4) * 8];
        unsigned ad = (unsigned)__cvta_generic_to_shared(p);
        asm volatile("ldmatrix.sync.aligned.m8n8.x4.shared.b16 {%0,%1,%2,%3}, [%4];"
            : "=r"(a[kc][0]), "=r"(a[kc][1]), "=r"(a[kc][2]), "=r"(a[kc][3]) : "r"(ad));
    }

    int r0 = row0 + wrow + (lane >> 2);
    int r1 = r0 + 8;
    float dv0 = (r0 < NN) ? g_dinv[gi][r0] : 0.f;
    float dv1 = (r1 < NN) ? g_dinv[gi][r1] : 0.f;

#pragma unroll
    for (int nt = 0; nt < NT; nt++) {
        float c0 = 0.f, c1 = 0.f, c2 = 0.f, c3 = 0.f;
#pragma unroll
        for (int kc = 0; kc < KCH; kc++) {
            int krow = kc * 16 + (lane & 7) + ((lane >> 3) & 1) * 8;
            const __half* pb = &Bs[krow * SB + nt * 8];
            unsigned bd = (unsigned)__cvta_generic_to_shared(pb);
            unsigned b0, b1;
            asm volatile("ldmatrix.sync.aligned.m8n8.x2.trans.shared.b16 {%0,%1}, [%2];"
                : "=r"(b0), "=r"(b1) : "r"(bd));
            asm volatile("mma.sync.aligned.m16n8k16.row.col.f32.f16.f16.f32 "
                "{%0,%1,%2,%3}, {%4,%5,%6,%7}, {%8,%9}, {%0,%1,%2,%3};"
                : "+f"(c0), "+f"(c1), "+f"(c2), "+f"(c3)
                : "r"(a[kc][0]), "r"(a[kc][1]), "r"(a[kc][2]), "r"(a[kc][3]),
                  "r"(b0), "r"(b1));
        }
        int cc = nt * 8 + (lane & 3) * 2;
        if (r0 < NN)
            *(__half2*)&g_h16[gi][r0 * C + cc] = __floats2half2_rn(c0 * dv0, c1 * dv0);
        if (r1 < NN)
            *(__half2*)&g_h16[gi][r1 * C + cc] = __floats2half2_rn(c2 * dv1, c3 * dv1);
    }
}

// ---------------- CSR aggregation: a16 = relu(dinv_d*(sum h' + h'_d) + b) ----------
// LPN threads per node; rowptr loaded once per node via shfl.
template <int C, bool RELU>
__global__ void agg_kernel(const float* __restrict__ b) {
    constexpr int LPN = C / 4;
    int gi = blockIdx.y;
    int tid = blockIdx.x * blockDim.x + threadIdx.x;
    int node = tid / LPN;
    int chunk = tid - node * LPN;
    if (node >= NN) return;
    // lane-0-of-node loads rowptr pair; broadcast within the node's lane group
    int lane = threadIdx.x & 31;
    int base_lane = lane - chunk;            // lane of chunk==0 for this node
    int s, e;
    {
        int v0 = 0, v1 = 0;
        if (chunk == 0) {
            v0 = g_rowptr[gi][node];
            v1 = g_rowptr[gi][node + 1];
        }
        s = __shfl_sync(0xffffffffu, v0, base_lane);
        e = __shfl_sync(0xffffffffu, v1, base_lane);
    }
    const uint2* h4 = (const uint2*)g_h16[gi];
    const int* ci = g_colidx[gi];
    float a0[4], a1[4];
#pragma unroll
    for (int j = 0; j < 4; j++) { a0[j] = 0.f; a1[j] = 0.f; }
    int i = s;
    for (; i + 1 < e; i += 2) {
        int c0 = ci[i], c1 = ci[i + 1];
        uint2 u0 = h4[c0 * LPN + chunk];
        uint2 u1 = h4[c1 * LPN + chunk];
        float2 f00 = __half22float2(*(const __half2*)&u0.x);
        float2 f01 = __half22float2(*(const __half2*)&u0.y);
        float2 f10 = __half22float2(*(const __half2*)&u1.x);
        float2 f11 = __half22float2(*(const __half2*)&u1.y);
        a0[0] += f00.x; a0[1] += f00.y; a0[2] += f01.x; a0[3] += f01.y;
        a1[0] += f10.x; a1[1] += f10.y; a1[2] += f11.x; a1[3] += f11.y;
    }
    if (i < e) {
        int c0 = ci[i];
        uint2 u0 = h4[c0 * LPN + chunk];
        float2 f00 = __half22float2(*(const __half2*)&u0.x);
        float2 f01 = __half22float2(*(const __half2*)&u0.y);
        a0[0] += f00.x; a0[1] += f00.y; a0[2] += f01.x; a0[3] += f01.y;
    }
    {
        uint2 us = h4[node * LPN + chunk];
        float2 fs0 = __half22float2(*(const __half2*)&us.x);
        float2 fs1 = __half22float2(*(const __half2*)&us.y);
        a0[0] += fs0.x; a0[1] += fs0.y; a0[2] += fs1.x; a0[3] += fs1.y;
    }
    float dv = g_dinv[gi][node];
    float4 bb = ((const float4*)b)[chunk];
    float4 res;
    res.x = dv * (a0[0] + a1[0]) + bb.x;
    res.y = dv * (a0[1] + a1[1]) + bb.y;
    res.z = dv * (a0[2] + a1[2]) + bb.z;
    res.w = dv * (a0[3] + a1[3]) + bb.w;
    if (RELU) {
        res.x = fmaxf(res.x, 0.f);
        res.y = fmaxf(res.y, 0.f);
        res.z = fmaxf(res.z, 0.f);
        res.w = fmaxf(res.w, 0.f);
    }
    __half2 o0 = __floats2half2_rn(res.x, res.y);
    __half2 o1 = __floats2half2_rn(res.z, res.w);
    uint2 ov;
    ov.x = *(unsigned*)&o0;
    ov.y = *(unsigned*)&o1;
    ((uint2*)g_a[gi])[node * LPN + chunk] = ov;
}

// ---------------- layer-3 aggregation (C=16) + column-sum fusion + deg re-zero ----
// Writes fp16 h3 (consumed by poolfinal).
__global__ void agg16_kernel(const float* __restrict__ b) {
    int gi = blockIdx.y;
    __shared__ float cssh[16];
    int t = threadIdx.x;
    if (t < 16) cssh[t] = 0.f;
    __syncthreads();
    int tid = blockIdx.x * 256 + t;
    int node = tid >> 2;
    int chunk = tid & 3;
    if (node < NN) {
        int lane = t & 31;
        int base_lane = lane - chunk;
        int s, e;
        {
            int v0 = 0, v1 = 0;
            if (chunk == 0) {
                v0 = g_rowptr[gi][node];
                v1 = g_rowptr[gi][node + 1];
            }
            s = __shfl_sync(0xffffffffu, v0, base_lane);
            e = __shfl_sync(0xffffffffu, v1, base_lane);
        }
        const uint2* h4 = (const uint2*)g_h16[gi];
        const int* ci = g_colidx[gi];
        float a0[4], a1[4];
#pragma unroll
        for (int j = 0; j < 4; j++) { a0[j] = 0.f; a1[j] = 0.f; }
        int i = s;
        for (; i + 1 < e; i += 2) {
            int c0 = ci[i], c1 = ci[i + 1];
            uint2 u0 = h4[c0 * 4 + chunk];
            uint2 u1 = h4[c1 * 4 + chunk];
            float2 f00 = __half22float2(*(const __half2*)&u0.x);
            float2 f01 = __half22float2(*(const __half2*)&u0.y);
            float2 f10 = __half22float2(*(const __half2*)&u1.x);
            float2 f11 = __half22float2(*(const __half2*)&u1.y);
            a0[0] += f00.x; a0[1] += f00.y; a0[2] += f01.x; a0[3] += f01.y;
            a1[0] += f10.x; a1[1] += f10.y; a1[2] += f11.x; a1[3] += f11.y;
        }
        if (i < e) {
            int c0 = ci[i];
            uint2 u0 = h4[c0 * 4 + chunk];
            float2 f00 = __half22float2(*(const __half2*)&u0.x);
            float2 f01 = __half22float2(*(const __half2*)&u0.y);
            a0[0] += f00.x; a0[1] += f00.y; a0[2] += f01.x; a0[3] += f01.y;
        }
        {
            uint2 us = h4[node * 4 + chunk];
            float2 fs0 = __half22float2(*(const __half2*)&us.x);
            float2 fs1 = __half22float2(*(const __half2*)&us.y);
            a0[0] += fs0.x; a0[1] += fs0.y; a0[2] += fs1.x; a0[3] += fs1.y;
        }
        float dv = g_dinv[gi][node];
        float4 bb = ((const float4*)b)[chunk];
        float4 res;
        res.x = dv * (a0[0] + a1[0]) + bb.x;
        res.y = dv * (a0[1] + a1[1]) + bb.y;
        res.z = dv * (a0[2] + a1[2]) + bb.z;
        res.w = dv * (a0[3] + a1[3]) + bb.w;
        // fp16 output for pooling
        __half2 o0 = __floats2half2_rn(res.x, res.y);
        __half2 o1 = __floats2half2_rn(res.z, res.w);
        uint2 ov;
        ov.x = *(unsigned*)&o0;
        ov.y = *(unsigned*)&o1;
        ((uint2*)g_a[gi])[node * 4 + chunk] = ov;
        atomicAdd(&cssh[chunk * 4 + 0], res.x);
        atomicAdd(&cssh[chunk * 4 + 1], res.y);
        atomicAdd(&cssh[chunk * 4 + 2], res.z);
        atomicAdd(&cssh[chunk * 4 + 3], res.w);
        if (chunk == 0) g_deg[gi][node] = 0;   // re-zero deg for next replay
    }
    __syncthreads();
    if (t < 16) atomicAdd(&g_cs[gi][t], cssh[t]);
}

// ---------------- attention pooling (fp16 h3, cvec fused) + NTN/MLP tail ----------
__global__ void poolfinal_kernel(const float* __restrict__ Wa,
                                 const float* __restrict__ Wt, const float* __restrict__ Wb,
                                 const float* __restrict__ bt, const float* __restrict__ Wfc,
                                 const float* __restrict__ bfc, const float* __restrict__ Wsc,
                                 const float* __restrict__ bsc, float* __restrict__ out) {
    int gi = blockIdx.y;
    __shared__ float csh[16];
    __shared__ float acc[16];
    int t = threadIdx.x;
    if (t < 16) {
        float a = 0.f;
        for (int i = 0; i < 16; i++) a += g_cs[gi][i] * Wa[i * 16 + t];
        csh[t] = tanhf(a * (1.0f / (float)NN));
        acc[t] = 0.f;
    }
    __syncthreads();
    float la[16];
#pragma unroll
    for (int j = 0; j < 16; j++) la[j] = 0.f;
    const uint4* base = (const uint4*)g_a[gi];   // 16 halves = 2 uint4 per node
    for (int n = blockIdx.x * blockDim.x + t; n < NN; n += gridDim.x * blockDim.x) {
        uint4 u0 = base[n * 2];
        uint4 u1 = base[n * 2 + 1];
        float hv[16];
        const __half2* q0 = (const __half2*)&u0;
        const __half2* q1 = (const __half2*)&u1;
#pragma unroll
        for (int j = 0; j < 4; j++) {
            float2 f0 = __half22float2(q0[j]);
            float2 f1 = __half22float2(q1[j]);
            hv[2 * j + 0] = f0.x;
            hv[2 * j + 1] = f0.y;
            hv[8 + 2 * j + 0] = f1.x;
            hv[8 + 2 * j + 1] = f1.y;
        }
        float dot = 0.f;
#pragma unroll
        for (int j = 0; j < 16; j++) dot += hv[j] * csh[j];
        float sg = 1.f / (1.f + __expf(-dot));
#pragma unroll
        for (int j = 0; j < 16; j++) la[j] += sg * hv[j];
    }
#pragma unroll
    for (int j = 0; j < 16; j++) atomicAdd(&acc[j], la[j]);
    __syncthreads();
    if (t < 16) atomicAdd(&g_evec[gi][t], acc[t]);

    __threadfence();
    __syncthreads();
    __shared__ int is_last;
    if (t == 0) is_last = (atomicAdd(&g_done, 1) == 2 * POOL_BLOCKS - 1) ? 1 : 0;
    __syncthreads();
    if (!is_last) return;

    volatile float* ev0 = g_evec[0];
    volatile float* ev1 = g_evec[1];
    __shared__ float e1s[16], e2s[16], tsh[16], s2[16];
    if (t < 16) {
        e1s[t] = ev0[t];
        e2s[t] = ev1[t];
    }
    __syncthreads();
    if (t < 16) {
        float bil = 0.f;
        for (int i = 0; i < 16; i++) {
            float e1v = e1s[i];
            for (int j = 0; j < 16; j++)
                bil += e1v * Wt[(i * 16 + j) * 16 + t] * e2s[j];
        }
        float blk = 0.f;
        for (int j = 0; j < 16; j++)
            blk += Wb[t * 32 + j] * e1s[j] + Wb[t * 32 + 16 + j] * e2s[j];
        float v = bil + blk + bt[t];
        tsh[t] = v > 0.f ? v : 0.f;
    }
    __syncthreads();
    if (t < 16) {
        float a = bfc[t];
        for (int j = 0; j < 16; j++) a += tsh[j] * Wfc[j * 16 + t];
        s2[t] = tanhf(a);
    }
    __syncthreads();
    if (t == 0) {
        float a = bsc[0];
        for (int j = 0; j < 16; j++) a += s2[j] * Wsc[j];
        out[0] = 1.f / (1.f + expf(-a));
    }
    __syncthreads();
    if (t < 32) {
        int g = t >> 4, j = t & 15;
        g_cs[g][j] = 0.f;
        g_evec[g][j] = 0.f;
    }
    if (t == 0) g_done = 0;
}

// ---------------- launch ----------------
extern "C" void kernel_launch(void* const* d_in, const int* in_sizes, int n_in,
                              void* d_out, int out_size) {
    const float* X1  = (const float*)d_in[0];
    const float* X2  = (const float*)d_in[1];
    const int*   E1  = (const int*)d_in[2];
    const int*   E2  = (const int*)d_in[3];
    const float* W1  = (const float*)d_in[4];
    const float* b1  = (const float*)d_in[5];
    const float* W2  = (const float*)d_in[6];
    const float* b2  = (const float*)d_in[7];
    const float* W3  = (const float*)d_in[8];
    const float* b3  = (const float*)d_in[9];
    const float* Wa  = (const float*)d_in[10];
    const float* Wt  = (const float*)d_in[11];
    const float* Wb  = (const float*)d_in[12];
    const float* bt  = (const float*)d_in[13];
    const float* Wfc = (const float*)d_in[14];
    const float* bfc = (const float*)d_in[15];
    const float* Wsc = (const float*)d_in[16];
    const float* bsc = (const float*)d_in[17];
    float* out = (float*)d_out;

    static cudaStream_t s_side = nullptr;
    static cudaEvent_t ev_fork = nullptr, ev_join = nullptr;
    if (s_side == nullptr) {
        cudaStreamCreateWithFlags(&s_side, cudaStreamNonBlocking);
        cudaEventCreateWithFlags(&ev_fork, cudaEventDisableTiming);
        cudaEventCreateWithFlags(&ev_join, cudaEventDisableTiming);
    }

    const int E4B = (NE / 4 + 255) / 256;

    hist_kernel<<<dim3(E4B, 2), 256>>>(E1, E2);

    cudaEventRecord(ev_fork, 0);
    cudaStreamWaitEvent(s_side, ev_fork, 0);
    gemm1_mma_kernel<<<dim3((NN + 127) / 128, 2), 256, 0, s_side>>>(X1, X2, W1);
    cudaEventRecord(ev_join, s_side);

    scanA_kernel<<<dim3(NBLK, 2), 256>>>();
    scanC_kernel<<<dim3(NBLK, 2), 256>>>();
    scatter_kernel<<<dim3(E4B, 2), 256>>>(E1, E2);

    cudaStreamWaitEvent(0, ev_join, 0);

    agg_kernel<64, true><<<dim3((NN * 16 + 255) / 256, 2), 256>>>(b1);
    gemm_mma_kernel<64, 32><<<dim3((NN + 127) / 128, 2), 256>>>(W2);
    agg_kernel<32, true><<<dim3((NN * 8 + 255) / 256, 2), 256>>>(b2);
    gemm_mma_kernel<32, 16><<<dim3((NN + 127) / 128, 2), 256>>>(W3);
    agg16_kernel<<<dim3((NN * 4 + 255) / 256, 2), 256>>>(b3);

    poolfinal_kernel<<<dim3(POOL_BLOCKS, 2), 256>>>(Wa, Wt, Wb, bt, Wfc, bfc, Wsc, bsc, out);
}